// round 11
// baseline (speedup 1.0000x reference)
#include <cuda_runtime.h>
#include <cstdint>

#define DIMIN 64
#define HID   170
#define C2    340
#define BATCH 4
#define HW    256

typedef unsigned long long f32x2_t;   // packed pair of fp32

// Intermediate buffer t = FFT-filtered projection, [4,340,256,256] fp32 (356MB scratch)
__device__ float g_t[(size_t)BATCH * C2 * HW * HW];
// Pre-transposed project_in weights (built by kPrep each launch)
__device__ float g_WinT[DIMIN * C2];   // [ic][oc]

// ---------- packed f32x2 helpers ----------
__device__ __forceinline__ f32x2_t ffma2(f32x2_t a, f32x2_t b, f32x2_t c) {
    f32x2_t d;
    asm("fma.rn.f32x2 %0, %1, %2, %3;" : "=l"(d) : "l"(a), "l"(b), "l"(c));
    return d;
}
__device__ __forceinline__ f32x2_t dup2(float v) {
    f32x2_t d;
    asm("mov.b64 %0, {%1, %1};" : "=l"(d) : "f"(v));
    return d;
}
__device__ __forceinline__ void unpack2(f32x2_t v, float& lo, float& hi) {
    asm("mov.b64 {%0, %1}, %2;" : "=f"(lo), "=f"(hi) : "l"(v));
}

// ---------- unrolled 8-point complex FFT (sgn=-1 fwd, +1 inv, unnormalized) ----------
__device__ __forceinline__ void fft8(float* xr, float* xi, float sgn) {
    float tr, ti;
    tr = xr[1]; xr[1] = xr[4]; xr[4] = tr;  ti = xi[1]; xi[1] = xi[4]; xi[4] = ti;
    tr = xr[3]; xr[3] = xr[6]; xr[6] = tr;  ti = xi[3]; xi[3] = xi[6]; xi[6] = ti;
    #pragma unroll
    for (int i = 0; i < 8; i += 2) {
        float ar = xr[i], ai = xi[i], br = xr[i+1], bi = xi[i+1];
        xr[i] = ar + br; xi[i] = ai + bi; xr[i+1] = ar - br; xi[i+1] = ai - bi;
    }
    #pragma unroll
    for (int i = 0; i < 8; i += 4) {
        { float ar = xr[i], ai = xi[i], br = xr[i+2], bi = xi[i+2];
          xr[i] = ar + br; xi[i] = ai + bi; xr[i+2] = ar - br; xi[i+2] = ai - bi; }
        { float ar = xr[i+1], ai = xi[i+1], br = xr[i+3], bi = xi[i+3];
          float wr = -sgn * bi, wi = sgn * br;
          xr[i+1] = ar + wr; xi[i+1] = ai + wi; xr[i+3] = ar - wr; xi[i+3] = ai - wi; }
    }
    const float c = 0.70710678118654752f;
    { float ar = xr[0], ai = xi[0], br = xr[4], bi = xi[4];
      xr[0] = ar + br; xi[0] = ai + bi; xr[4] = ar - br; xi[4] = ai - bi; }
    { float ar = xr[1], ai = xi[1], br = xr[5], bi = xi[5];
      float wr = c * (br - sgn * bi), wi = c * (bi + sgn * br);
      xr[1] = ar + wr; xi[1] = ai + wi; xr[5] = ar - wr; xi[5] = ai - wi; }
    { float ar = xr[2], ai = xi[2], br = xr[6], bi = xi[6];
      float wr = -sgn * bi, wi = sgn * br;
      xr[2] = ar + wr; xi[2] = ai + wi; xr[6] = ar - wr; xi[6] = ai - wi; }
    { float ar = xr[3], ai = xi[3], br = xr[7], bi = xi[7];
      float wr = c * (-br - sgn * bi), wi = c * (-bi + sgn * br);
      xr[3] = ar + wr; xi[3] = ai + wi; xr[7] = ar - wr; xi[7] = ai - wi; }
}

__device__ __forceinline__ void fft_filter_store(int oc, const f32x2_t* acc,
                                                 const float* __restrict__ filt,
                                                 int b, int ph, int pw) {
    float a[64];
    #pragma unroll
    for (int j = 0; j < 32; j++) unpack2(acc[j], a[2*j], a[2*j+1]);

    float re[8][5], im[8][5];
    #pragma unroll
    for (int r = 0; r < 8; r++) {
        float xr[8], xi[8];
        #pragma unroll
        for (int c = 0; c < 8; c++) { xr[c] = a[r*8 + c]; xi[c] = 0.f; }
        fft8(xr, xi, -1.f);
        #pragma unroll
        for (int k = 0; k < 5; k++) { re[r][k] = xr[k]; im[r][k] = xi[k]; }
    }
    const float* fch = filt + oc * 40;
    #pragma unroll
    for (int k = 0; k < 5; k++) {
        float xr[8], xi[8];
        #pragma unroll
        for (int r = 0; r < 8; r++) { xr[r] = re[r][k]; xi[r] = im[r][k]; }
        fft8(xr, xi, -1.f);
        #pragma unroll
        for (int r = 0; r < 8; r++) {
            float f = __ldg(fch + r*5 + k) * (1.f / 64.f);
            xr[r] *= f; xi[r] *= f;
        }
        fft8(xr, xi, 1.f);
        #pragma unroll
        for (int r = 0; r < 8; r++) { re[r][k] = xr[r]; im[r][k] = xi[r]; }
    }
    float* ob = g_t + (((size_t)(b * C2 + oc) * HW + ph*8) * HW + pw*8);
    #pragma unroll
    for (int r = 0; r < 8; r++) {
        float xr[8], xi[8];
        #pragma unroll
        for (int k = 0; k < 5; k++) { xr[k] = re[r][k]; xi[k] = im[r][k]; }
        xr[5] = re[r][3]; xi[5] = -im[r][3];
        xr[6] = re[r][2]; xi[6] = -im[r][2];
        xr[7] = re[r][1]; xi[7] = -im[r][1];
        fft8(xr, xi, 1.f);
        float4 v0 = make_float4(xr[0], xr[1], xr[2], xr[3]);
        float4 v1 = make_float4(xr[4], xr[5], xr[6], xr[7]);
        *(float4*)(ob + (size_t)r * HW)     = v0;
        *(float4*)(ob + (size_t)r * HW + 4) = v1;
    }
}

// ================= Prep: transpose project_in weights once per launch =================
__global__ void kPrep(const float* __restrict__ Win) {
    int i = blockIdx.x * 256 + threadIdx.x;
    if (i < C2 * DIMIN) {
        int oc = i / DIMIN, ic = i % DIMIN;
        g_WinT[ic * C2 + oc] = Win[i];
    }
}

// ================= Kernel A: project_in (64->340) + patch FFT filter =================
// Weights read directly from L1-resident g_WinT (measured ~96us faster than
// per-block smem staging via the R8-vs-R9 A/B).
#define KA_THREADS 176
#define SMEM_A (32 * KA_THREADS * 8)    // spill region 45056B (>= sX 16KB, reused)

__global__ void __launch_bounds__(KA_THREADS, 2)
kA(const float* __restrict__ x, const float* __restrict__ filt) {
    extern __shared__ float sm[];
    float* sX = sm;             // [ic][64 pix] (16KB, overlapped later by spill)

    const int t  = threadIdx.x;
    const int pw = blockIdx.x, ph = blockIdx.y, b = blockIdx.z;

    for (int i = t; i < 1024; i += KA_THREADS) {
        int ic = i >> 4, rr = (i >> 1) & 7, half = i & 1;
        float4 v = *(const float4*)(x + (((size_t)(b * DIMIN + ic) * HW + ph*8 + rr) * HW + pw*8 + half*4));
        *(float4*)(sX + ic*64 + rr*8 + half*4) = v;
    }
    __syncthreads();

    const int oc0 = t;
    const int oc1 = t + KA_THREADS;
    const bool has1 = (oc1 < C2);
    const int oc1c = has1 ? oc1 : 0;

    f32x2_t a0[32], a1[32];
    #pragma unroll
    for (int j = 0; j < 32; j++) { a0[j] = 0ull; a1[j] = 0ull; }

    const ulonglong2* sX4 = (const ulonglong2*)sX;
    #pragma unroll 2
    for (int ic = 0; ic < 64; ic++) {
        f32x2_t w0 = dup2(__ldg(g_WinT + ic * C2 + oc0));
        f32x2_t w1 = dup2(__ldg(g_WinT + ic * C2 + oc1c));
        #pragma unroll
        for (int j = 0; j < 16; j++) {
            ulonglong2 xv = sX4[ic * 16 + j];
            a0[2*j]   = ffma2(w0, xv.x, a0[2*j]);
            a0[2*j+1] = ffma2(w0, xv.y, a0[2*j+1]);
            a1[2*j]   = ffma2(w1, xv.x, a1[2*j]);
            a1[2*j+1] = ffma2(w1, xv.y, a1[2*j+1]);
        }
    }
    __syncthreads();   // all GEMM reads of sX done; reuse smem as spill

    f32x2_t* sSpill = (f32x2_t*)sm;   // [32][KA_THREADS] = 45056B
    #pragma unroll
    for (int j = 0; j < 32; j++) sSpill[j * KA_THREADS + t] = a1[j];

    fft_filter_store(oc0, a0, filt, b, ph, pw);

    if (has1) {
        f32x2_t a1b[32];
        #pragma unroll
        for (int j = 0; j < 32; j++) a1b[j] = sSpill[j * KA_THREADS + t];
        fft_filter_store(oc1, a1b, filt, b, ph, pw);
    }
}

// ============ Kernel B: depthwise 3x3 + GELU gate + project_out (170->64) ============
// R10 structure; ONLY the halo loader changed: per-thread slot indices (2 fixed
// positions) precomputed once, channel-major unrolled loop — no div/mod in the
// hot loop, 40 independent LDG in flight per thread.
#define SWO_F   (HID * 64)
#define SDW_F   (C2 * 12)
#define ST_F    (20 * 324)
#define SG_F    (10 * 256)
#define SMEM_B  ((SWO_F + SDW_F + ST_F + SG_F) * 4)   // 96000 bytes

__global__ void __launch_bounds__(256, 2)
kB(const float* __restrict__ Wdw, const float* __restrict__ Wout,
   float* __restrict__ out) {
    extern __shared__ float sm[];
    float* sWo = sm;                          // transposed: [hc][64 o]
    float* sDw = sm + SWO_F;                  // [340][12] (9 used)
    float* sT  = sm + SWO_F + SDW_F;          // [20][18*18]
    float* sG  = sm + SWO_F + SDW_F + ST_F;   // [10][256]

    const int t  = threadIdx.x;
    const int tx = t & 15, ty = t >> 4;
    const int bx = blockIdx.x * 16, by = blockIdx.y * 16, b = blockIdx.z;

    // GEMM-phase thread mapping: warp = output group of 8, lane = pixel group of 8
    const int outg = t >> 5;
    const int p0   = (t & 31) * 8;

    // ---- halo slot mapping, computed ONCE: slot1 = t, slot2 = t + 256 (t<68) ----
    const int ly1 = t / 18, lx1 = t % 18;
    const int ly2 = (t + 256) / 18, lx2 = (t + 256) % 18;
    const bool ok1 = (by - 1 + ly1 >= 0) && (by - 1 + ly1 < HW) &&
                     (bx - 1 + lx1 >= 0) && (bx - 1 + lx1 < HW);
    const bool has2 = (t < 68);
    const bool ok2 = has2 && (by - 1 + ly2 >= 0) && (by - 1 + ly2 < HW) &&
                     (bx - 1 + lx2 >= 0) && (bx - 1 + lx2 < HW);
    const int off1 = (by - 1 + ly1) * HW + (bx - 1 + lx1);
    const int off2 = (by - 1 + ly2) * HW + (bx - 1 + lx2);
    const float* gbase = g_t + (size_t)b * C2 * (HW * HW);

    for (int i = t; i < DIMIN * HID; i += 256) {
        int o = i / HID, hc = i % HID;
        sWo[hc * 64 + o] = Wout[i];
    }
    for (int i = t; i < C2 * 9; i += 256) {
        int ch = i / 9, j = i % 9;
        sDw[ch * 12 + j] = Wdw[i];
    }

    f32x2_t acc[8][4];
    #pragma unroll
    for (int o = 0; o < 8; o++)
        #pragma unroll
        for (int pp = 0; pp < 4; pp++) acc[o][pp] = 0ull;

    for (int cc = 0; cc < 17; cc++) {
        __syncthreads();  // sT safe to overwrite; first iter: orders sWo/sDw
        // ---- halo load: channel-major, precomputed offsets, batched LDG ----
        {
            const float* c0 = gbase + (size_t)(cc * 10) * (HW * HW);        // gate-a chans
            const float* c1 = gbase + (size_t)(HID + cc * 10) * (HW * HW);  // gate-b chans
            #pragma unroll 5
            for (int ch = 0; ch < 10; ch++) {
                const float* pa = c0 + (size_t)ch * (HW * HW);
                const float* pb = c1 + (size_t)ch * (HW * HW);
                sT[ch * 324 + t]          = ok1 ? pa[off1] : 0.f;
                sT[(ch + 10) * 324 + t]   = ok1 ? pb[off1] : 0.f;
                if (has2) {
                    sT[ch * 324 + 256 + t]        = ok2 ? pa[off2] : 0.f;
                    sT[(ch + 10) * 324 + 256 + t] = ok2 ? pb[off2] : 0.f;
                }
            }
        }
        __syncthreads();

        // -------- phase B: dw conv + exact GELU gate, stage g to sG (as measured) ----
        #pragma unroll 2
        for (int c = 0; c < 10; c++) {
            int hc = cc * 10 + c;
            const float* wp1 = sDw + hc * 12;
            const float* wp2 = sDw + (hc + HID) * 12;
            float4 w1a = *(const float4*)wp1;
            float4 w1b = *(const float4*)(wp1 + 4);
            float  w1c = wp1[8];
            float4 w2a = *(const float4*)wp2;
            float4 w2b = *(const float4*)(wp2 + 4);
            float  w2c = wp2[8];
            const float* t1 = sT + c * 324 + ty * 18 + tx;
            const float* t2 = t1 + 10 * 324;
            float d1, d2;
            d1 = t1[0]  * w1a.x; d2 = t2[0]  * w2a.x;
            d1 = fmaf(t1[1],  w1a.y, d1); d2 = fmaf(t2[1],  w2a.y, d2);
            d1 = fmaf(t1[2],  w1a.z, d1); d2 = fmaf(t2[2],  w2a.z, d2);
            d1 = fmaf(t1[18], w1a.w, d1); d2 = fmaf(t2[18], w2a.w, d2);
            d1 = fmaf(t1[19], w1b.x, d1); d2 = fmaf(t2[19], w2b.x, d2);
            d1 = fmaf(t1[20], w1b.y, d1); d2 = fmaf(t2[20], w2b.y, d2);
            d1 = fmaf(t1[36], w1b.z, d1); d2 = fmaf(t2[36], w2b.z, d2);
            d1 = fmaf(t1[37], w1b.w, d1); d2 = fmaf(t2[37], w2b.w, d2);
            d1 = fmaf(t1[38], w1c,   d1); d2 = fmaf(t2[38], w2c,   d2);
            float g = 0.5f * d1 * (1.f + erff(d1 * 0.70710678118654752f)) * d2;
            sG[c * 256 + t] = g;
        }
        __syncthreads();

        // -------- phase C: projection GEMM update (k = 10) (as measured) --------
        #pragma unroll
        for (int c = 0; c < 10; c++) {
            int hc = cc * 10 + c;
            const ulonglong2* gp = (const ulonglong2*)(sG + c * 256 + p0);
            ulonglong2 gv0 = gp[0], gv1 = gp[1];
            const float4* wp = (const float4*)(sWo + hc * 64 + outg * 8);
            float4 w0 = wp[0], w1 = wp[1];
            f32x2_t wd[8];
            wd[0] = dup2(w0.x); wd[1] = dup2(w0.y); wd[2] = dup2(w0.z); wd[3] = dup2(w0.w);
            wd[4] = dup2(w1.x); wd[5] = dup2(w1.y); wd[6] = dup2(w1.z); wd[7] = dup2(w1.w);
            #pragma unroll
            for (int o = 0; o < 8; o++) {
                acc[o][0] = ffma2(wd[o], gv0.x, acc[o][0]);
                acc[o][1] = ffma2(wd[o], gv0.y, acc[o][1]);
                acc[o][2] = ffma2(wd[o], gv1.x, acc[o][2]);
                acc[o][3] = ffma2(wd[o], gv1.y, acc[o][3]);
            }
        }
    }

    // -------- store: thread owns outputs (outg*8..+7) x pixels (p0..p0+7) --------
    const int py  = p0 >> 4;
    const int px0 = p0 & 15;
    #pragma unroll
    for (int o = 0; o < 8; o++) {
        int oc = outg * 8 + o;
        float v[8];
        #pragma unroll
        for (int pp = 0; pp < 4; pp++) unpack2(acc[o][pp], v[2*pp], v[2*pp+1]);
        float* ob = out + (((size_t)(b * DIMIN + oc)) * HW + (by + py)) * HW + (bx + px0);
        *(float4*)(ob)     = make_float4(v[0], v[1], v[2], v[3]);
        *(float4*)(ob + 4) = make_float4(v[4], v[5], v[6], v[7]);
    }
}

// ======================== launch ========================
extern "C" void kernel_launch(void* const* d_in, const int* in_sizes, int n_in,
                              void* d_out, int out_size) {
    (void)in_sizes; (void)n_in; (void)out_size;
    const float* x    = (const float*)d_in[0];
    const float* Win  = (const float*)d_in[1];
    const float* Wdw  = (const float*)d_in[2];
    const float* filt = (const float*)d_in[3];
    const float* Wout = (const float*)d_in[4];
    float* out = (float*)d_out;

    cudaFuncSetAttribute(kA, cudaFuncAttributeMaxDynamicSharedMemorySize, SMEM_A);
    cudaFuncSetAttribute(kB, cudaFuncAttributeMaxDynamicSharedMemorySize, SMEM_B);

    kPrep<<<(C2 * DIMIN + 255) / 256, 256>>>(Win);
    kA<<<dim3(32, 32, BATCH), KA_THREADS, SMEM_A>>>(x, filt);
    kB<<<dim3(16, 16, BATCH), 256, SMEM_B>>>(Wdw, Wout, out);
}

// round 12
// speedup vs baseline: 1.4115x; 1.4115x over previous
#include <cuda_runtime.h>
#include <cstdint>

#define DIMIN 64
#define HID   170
#define C2    340
#define BATCH 4
#define HW    256

typedef unsigned long long f32x2_t;   // packed pair of fp32

// Intermediate buffer t = FFT-filtered projection, [4,340,256,256] fp32 (356MB scratch)
__device__ float g_t[(size_t)BATCH * C2 * HW * HW];

// ---------- packed f32x2 helpers ----------
__device__ __forceinline__ f32x2_t ffma2(f32x2_t a, f32x2_t b, f32x2_t c) {
    f32x2_t d;
    asm("fma.rn.f32x2 %0, %1, %2, %3;" : "=l"(d) : "l"(a), "l"(b), "l"(c));
    return d;
}
__device__ __forceinline__ f32x2_t dup2(float v) {
    f32x2_t d;
    asm("mov.b64 %0, {%1, %1};" : "=l"(d) : "f"(v));
    return d;
}
__device__ __forceinline__ void unpack2(f32x2_t v, float& lo, float& hi) {
    asm("mov.b64 {%0, %1}, %2;" : "=f"(lo), "=f"(hi) : "l"(v));
}

// ---------- unrolled 8-point complex FFT (sgn=-1 fwd, +1 inv, unnormalized) ----------
__device__ __forceinline__ void fft8(float* xr, float* xi, float sgn) {
    float tr, ti;
    tr = xr[1]; xr[1] = xr[4]; xr[4] = tr;  ti = xi[1]; xi[1] = xi[4]; xi[4] = ti;
    tr = xr[3]; xr[3] = xr[6]; xr[6] = tr;  ti = xi[3]; xi[3] = xi[6]; xi[6] = ti;
    #pragma unroll
    for (int i = 0; i < 8; i += 2) {
        float ar = xr[i], ai = xi[i], br = xr[i+1], bi = xi[i+1];
        xr[i] = ar + br; xi[i] = ai + bi; xr[i+1] = ar - br; xi[i+1] = ai - bi;
    }
    #pragma unroll
    for (int i = 0; i < 8; i += 4) {
        { float ar = xr[i], ai = xi[i], br = xr[i+2], bi = xi[i+2];
          xr[i] = ar + br; xi[i] = ai + bi; xr[i+2] = ar - br; xi[i+2] = ai - bi; }
        { float ar = xr[i+1], ai = xi[i+1], br = xr[i+3], bi = xi[i+3];
          float wr = -sgn * bi, wi = sgn * br;
          xr[i+1] = ar + wr; xi[i+1] = ai + wi; xr[i+3] = ar - wr; xi[i+3] = ai - wi; }
    }
    const float c = 0.70710678118654752f;
    { float ar = xr[0], ai = xi[0], br = xr[4], bi = xi[4];
      xr[0] = ar + br; xi[0] = ai + bi; xr[4] = ar - br; xi[4] = ai - bi; }
    { float ar = xr[1], ai = xi[1], br = xr[5], bi = xi[5];
      float wr = c * (br - sgn * bi), wi = c * (bi + sgn * br);
      xr[1] = ar + wr; xi[1] = ai + wi; xr[5] = ar - wr; xi[5] = ai - wi; }
    { float ar = xr[2], ai = xi[2], br = xr[6], bi = xi[6];
      float wr = -sgn * bi, wi = sgn * br;
      xr[2] = ar + wr; xi[2] = ai + wi; xr[6] = ar - wr; xi[6] = ai - wi; }
    { float ar = xr[3], ai = xi[3], br = xr[7], bi = xi[7];
      float wr = c * (-br - sgn * bi), wi = c * (-bi + sgn * br);
      xr[3] = ar + wr; xi[3] = ai + wi; xr[7] = ar - wr; xi[7] = ai - wi; }
}

__device__ __forceinline__ void fft_filter_store(int oc, const f32x2_t* acc,
                                                 const float* __restrict__ filt,
                                                 int b, int ph, int pw) {
    float a[64];
    #pragma unroll
    for (int j = 0; j < 32; j++) unpack2(acc[j], a[2*j], a[2*j+1]);

    float re[8][5], im[8][5];
    #pragma unroll
    for (int r = 0; r < 8; r++) {
        float xr[8], xi[8];
        #pragma unroll
        for (int c = 0; c < 8; c++) { xr[c] = a[r*8 + c]; xi[c] = 0.f; }
        fft8(xr, xi, -1.f);
        #pragma unroll
        for (int k = 0; k < 5; k++) { re[r][k] = xr[k]; im[r][k] = xi[k]; }
    }
    const float* fch = filt + oc * 40;
    #pragma unroll
    for (int k = 0; k < 5; k++) {
        float xr[8], xi[8];
        #pragma unroll
        for (int r = 0; r < 8; r++) { xr[r] = re[r][k]; xi[r] = im[r][k]; }
        fft8(xr, xi, -1.f);
        #pragma unroll
        for (int r = 0; r < 8; r++) {
            float f = __ldg(fch + r*5 + k) * (1.f / 64.f);
            xr[r] *= f; xi[r] *= f;
        }
        fft8(xr, xi, 1.f);
        #pragma unroll
        for (int r = 0; r < 8; r++) { re[r][k] = xr[r]; im[r][k] = xi[r]; }
    }
    float* ob = g_t + (((size_t)(b * C2 + oc) * HW + ph*8) * HW + pw*8);
    #pragma unroll
    for (int r = 0; r < 8; r++) {
        float xr[8], xi[8];
        #pragma unroll
        for (int k = 0; k < 5; k++) { xr[k] = re[r][k]; xi[k] = im[r][k]; }
        xr[5] = re[r][3]; xi[5] = -im[r][3];
        xr[6] = re[r][2]; xi[6] = -im[r][2];
        xr[7] = re[r][1]; xi[7] = -im[r][1];
        fft8(xr, xi, 1.f);
        float4 v0 = make_float4(xr[0], xr[1], xr[2], xr[3]);
        float4 v1 = make_float4(xr[4], xr[5], xr[6], xr[7]);
        *(float4*)(ob + (size_t)r * HW)     = v0;
        *(float4*)(ob + (size_t)r * HW + 4) = v1;
    }
}

// ================= Kernel A: project_in (64->340) + patch FFT filter =================
// (byte-identical to the R5 kernel that measured 1263us total)
#define KA_THREADS 176
#define SMEM_A (64*64*4 + C2*DIMIN*4)   // patch (16KB) + transposed W_in (87KB)

__global__ void __launch_bounds__(KA_THREADS, 2)
kA(const float* __restrict__ x, const float* __restrict__ Win,
   const float* __restrict__ filt) {
    extern __shared__ float sm[];
    float* sX = sm;             // [ic][64 pix]
    float* sW = sm + 64 * 64;   // transposed: [ic][oc]

    const int t  = threadIdx.x;
    const int pw = blockIdx.x, ph = blockIdx.y, b = blockIdx.z;

    for (int i = t; i < 1024; i += KA_THREADS) {
        int ic = i >> 4, rr = (i >> 1) & 7, half = i & 1;
        float4 v = *(const float4*)(x + (((size_t)(b * DIMIN + ic) * HW + ph*8 + rr) * HW + pw*8 + half*4));
        *(float4*)(sX + ic*64 + rr*8 + half*4) = v;
    }
    for (int i = t; i < C2 * DIMIN; i += KA_THREADS) {
        int oc = i >> 6, ic = i & 63;
        sW[ic * C2 + oc] = Win[i];
    }
    __syncthreads();

    const int oc0 = t;
    const int oc1 = t + KA_THREADS;
    const bool has1 = (oc1 < C2);
    const int oc1c = has1 ? oc1 : 0;

    f32x2_t a0[32], a1[32];
    #pragma unroll
    for (int j = 0; j < 32; j++) { a0[j] = 0ull; a1[j] = 0ull; }

    const ulonglong2* sX4 = (const ulonglong2*)sX;
    #pragma unroll 2
    for (int ic = 0; ic < 64; ic++) {
        f32x2_t w0 = dup2(sW[ic * C2 + oc0]);
        f32x2_t w1 = dup2(sW[ic * C2 + oc1c]);
        #pragma unroll
        for (int j = 0; j < 16; j++) {
            ulonglong2 xv = sX4[ic * 16 + j];
            a0[2*j]   = ffma2(w0, xv.x, a0[2*j]);
            a0[2*j+1] = ffma2(w0, xv.y, a0[2*j+1]);
            a1[2*j]   = ffma2(w1, xv.x, a1[2*j]);
            a1[2*j+1] = ffma2(w1, xv.y, a1[2*j+1]);
        }
    }
    __syncthreads();

    f32x2_t* sSpill = (f32x2_t*)sm;   // [32][KA_THREADS]
    #pragma unroll
    for (int j = 0; j < 32; j++) sSpill[j * KA_THREADS + t] = a1[j];

    fft_filter_store(oc0, a0, filt, b, ph, pw);

    if (has1) {
        f32x2_t a1b[32];
        #pragma unroll
        for (int j = 0; j < 32; j++) a1b[j] = sSpill[j * KA_THREADS + t];
        fft_filter_store(oc1, a1b, filt, b, ph, pw);
    }
}

// ============ Kernel B: depthwise 3x3 + GELU gate + project_out (170->64) ============
// R5 structure exactly; ONE change: halo loader uses precomputed per-thread slots
// (no div/mod/bounds math in the chunk loop; batched independent LDG).
#define SG_OFF   (HID*64 + C2*9 + 20*324)            // floats
#define SMEM_B   ((SG_OFF + 10*256) * 4)             // 91920 bytes

__global__ void __launch_bounds__(256, 2)
kB(const float* __restrict__ Wdw, const float* __restrict__ Wout,
   float* __restrict__ out) {
    extern __shared__ float sm[];
    float* sWo = sm;                 // transposed: [hc][64 o]
    float* sDw = sm + HID * 64;      // [340*9]
    float* sT  = sDw + C2 * 9;       // [20][18*18]
    float* sG  = sm + SG_OFF;        // [10][256]

    const int t  = threadIdx.x;
    const int tx = t & 15, ty = t >> 4;
    const int bx = blockIdx.x * 16, by = blockIdx.y * 16, b = blockIdx.z;

    // GEMM-phase thread mapping: warp = output group of 8, lane = pixel group of 8
    const int outg = t >> 5;
    const int p0   = (t & 31) * 8;

    // ---- halo slot mapping, computed ONCE: slot1 = t, slot2 = t + 256 (t<68) ----
    const int ly1 = t / 18, lx1 = t % 18;
    const int ly2 = (t + 256) / 18, lx2 = (t + 256) % 18;
    const bool ok1 = (by - 1 + ly1 >= 0) && (by - 1 + ly1 < HW) &&
                     (bx - 1 + lx1 >= 0) && (bx - 1 + lx1 < HW);
    const bool has2 = (t < 68);
    const bool ok2 = has2 && (by - 1 + ly2 >= 0) && (by - 1 + ly2 < HW) &&
                     (bx - 1 + lx2 >= 0) && (bx - 1 + lx2 < HW);
    const int off1 = (by - 1 + ly1) * HW + (bx - 1 + lx1);
    const int off2 = (by - 1 + ly2) * HW + (bx - 1 + lx2);
    const float* gbase = g_t + (size_t)b * C2 * (HW * HW);

    for (int i = t; i < DIMIN * HID; i += 256) {
        int o = i / HID, hc = i % HID;
        sWo[hc * 64 + o] = Wout[i];
    }
    for (int i = t; i < C2 * 9; i += 256) sDw[i] = Wdw[i];

    f32x2_t acc[8][4];
    #pragma unroll
    for (int o = 0; o < 8; o++)
        #pragma unroll
        for (int pp = 0; pp < 4; pp++) acc[o][pp] = 0ull;

    for (int cc = 0; cc < 17; cc++) {
        __syncthreads();  // sT safe to overwrite (prev B done); first iter: orders sWo/sDw
        // ---- halo load: channel-major, precomputed offsets, batched LDG ----
        {
            const float* c0 = gbase + (size_t)(cc * 10) * (HW * HW);        // gate-a chans
            const float* c1 = gbase + (size_t)(HID + cc * 10) * (HW * HW);  // gate-b chans
            #pragma unroll 5
            for (int ch = 0; ch < 10; ch++) {
                const float* pa = c0 + (size_t)ch * (HW * HW);
                const float* pb = c1 + (size_t)ch * (HW * HW);
                sT[ch * 324 + t]        = ok1 ? pa[off1] : 0.f;
                sT[(ch + 10) * 324 + t] = ok1 ? pb[off1] : 0.f;
                if (has2) {
                    sT[ch * 324 + 256 + t]        = ok2 ? pa[off2] : 0.f;
                    sT[(ch + 10) * 324 + 256 + t] = ok2 ? pb[off2] : 0.f;
                }
            }
        }
        __syncthreads();

        // -------- phase B: dw conv + exact GELU gate, stage g to sG (as measured) ----
        #pragma unroll 2
        for (int c = 0; c < 10; c++) {
            int hc = cc * 10 + c;
            const float* w1 = sDw + hc * 9;
            const float* w2 = sDw + (hc + HID) * 9;
            const float* t1 = sT + c * 324 + ty * 18 + tx;
            const float* t2 = t1 + 10 * 324;
            float d1 = 0.f, d2 = 0.f;
            #pragma unroll
            for (int ky = 0; ky < 3; ky++)
                #pragma unroll
                for (int kx = 0; kx < 3; kx++) {
                    d1 = fmaf(w1[ky*3 + kx], t1[ky*18 + kx], d1);
                    d2 = fmaf(w2[ky*3 + kx], t2[ky*18 + kx], d2);
                }
            float g = 0.5f * d1 * (1.f + erff(d1 * 0.70710678118654752f)) * d2;
            sG[c * 256 + t] = g;
        }
        __syncthreads();

        // -------- phase C: projection GEMM update (k = 10) (as measured) --------
        #pragma unroll
        for (int c = 0; c < 10; c++) {
            int hc = cc * 10 + c;
            const ulonglong2* gp = (const ulonglong2*)(sG + c * 256 + p0);
            ulonglong2 gv0 = gp[0], gv1 = gp[1];
            const float4* wp = (const float4*)(sWo + hc * 64 + outg * 8);
            float4 w0 = wp[0], w1 = wp[1];
            f32x2_t wd[8];
            wd[0] = dup2(w0.x); wd[1] = dup2(w0.y); wd[2] = dup2(w0.z); wd[3] = dup2(w0.w);
            wd[4] = dup2(w1.x); wd[5] = dup2(w1.y); wd[6] = dup2(w1.z); wd[7] = dup2(w1.w);
            #pragma unroll
            for (int o = 0; o < 8; o++) {
                acc[o][0] = ffma2(wd[o], gv0.x, acc[o][0]);
                acc[o][1] = ffma2(wd[o], gv0.y, acc[o][1]);
                acc[o][2] = ffma2(wd[o], gv1.x, acc[o][2]);
                acc[o][3] = ffma2(wd[o], gv1.y, acc[o][3]);
            }
        }
    }

    // -------- store: thread owns outputs (outg*8..+7) x pixels (p0..p0+7) --------
    const int py  = p0 >> 4;
    const int px0 = p0 & 15;
    #pragma unroll
    for (int o = 0; o < 8; o++) {
        int oc = outg * 8 + o;
        float v[8];
        #pragma unroll
        for (int pp = 0; pp < 4; pp++) unpack2(acc[o][pp], v[2*pp], v[2*pp+1]);
        float* ob = out + (((size_t)(b * DIMIN + oc)) * HW + (by + py)) * HW + (bx + px0);
        *(float4*)(ob)     = make_float4(v[0], v[1], v[2], v[3]);
        *(float4*)(ob + 4) = make_float4(v[4], v[5], v[6], v[7]);
    }
}

// ======================== launch ========================
extern "C" void kernel_launch(void* const* d_in, const int* in_sizes, int n_in,
                              void* d_out, int out_size) {
    (void)in_sizes; (void)n_in; (void)out_size;
    const float* x    = (const float*)d_in[0];
    const float* Win  = (const float*)d_in[1];
    const float* Wdw  = (const float*)d_in[2];
    const float* filt = (const float*)d_in[3];
    const float* Wout = (const float*)d_in[4];
    float* out = (float*)d_out;

    cudaFuncSetAttribute(kA, cudaFuncAttributeMaxDynamicSharedMemorySize, SMEM_A);
    cudaFuncSetAttribute(kB, cudaFuncAttributeMaxDynamicSharedMemorySize, SMEM_B);

    kA<<<dim3(32, 32, BATCH), KA_THREADS, SMEM_A>>>(x, Win, filt);
    kB<<<dim3(16, 16, BATCH), 256, SMEM_B>>>(Wdw, Wout, out);
}

// round 13
// speedup vs baseline: 1.5702x; 1.1125x over previous
#include <cuda_runtime.h>
#include <cstdint>

#define DIMIN 64
#define HID   170
#define C2    340
#define BATCH 4
#define HW    256

typedef unsigned long long f32x2_t;   // packed pair of fp32

// Intermediate buffer t = FFT-filtered projection, [4,340,256,256] fp32 (356MB scratch)
__device__ float g_t[(size_t)BATCH * C2 * HW * HW];

// ---------- packed f32x2 helpers ----------
__device__ __forceinline__ f32x2_t ffma2(f32x2_t a, f32x2_t b, f32x2_t c) {
    f32x2_t d;
    asm("fma.rn.f32x2 %0, %1, %2, %3;" : "=l"(d) : "l"(a), "l"(b), "l"(c));
    return d;
}
__device__ __forceinline__ f32x2_t dup2(float v) {
    f32x2_t d;
    asm("mov.b64 %0, {%1, %1};" : "=l"(d) : "f"(v));
    return d;
}
__device__ __forceinline__ void unpack2(f32x2_t v, float& lo, float& hi) {
    asm("mov.b64 {%0, %1}, %2;" : "=f"(lo), "=f"(hi) : "l"(v));
}

// ---------- cp.async helpers ----------
__device__ __forceinline__ void cpasync4(unsigned dst, const float* src, int szbytes) {
    asm volatile("cp.async.ca.shared.global [%0], [%1], 4, %2;"
                 :: "r"(dst), "l"(src), "r"(szbytes) : "memory");
}
__device__ __forceinline__ void cpasync_commit() {
    asm volatile("cp.async.commit_group;" ::: "memory");
}
__device__ __forceinline__ void cpasync_wait1() {
    asm volatile("cp.async.wait_group 1;" ::: "memory");
}

// ---------- unrolled 8-point complex FFT (sgn=-1 fwd, +1 inv, unnormalized) ----------
__device__ __forceinline__ void fft8(float* xr, float* xi, float sgn) {
    float tr, ti;
    tr = xr[1]; xr[1] = xr[4]; xr[4] = tr;  ti = xi[1]; xi[1] = xi[4]; xi[4] = ti;
    tr = xr[3]; xr[3] = xr[6]; xr[6] = tr;  ti = xi[3]; xi[3] = xi[6]; xi[6] = ti;
    #pragma unroll
    for (int i = 0; i < 8; i += 2) {
        float ar = xr[i], ai = xi[i], br = xr[i+1], bi = xi[i+1];
        xr[i] = ar + br; xi[i] = ai + bi; xr[i+1] = ar - br; xi[i+1] = ai - bi;
    }
    #pragma unroll
    for (int i = 0; i < 8; i += 4) {
        { float ar = xr[i], ai = xi[i], br = xr[i+2], bi = xi[i+2];
          xr[i] = ar + br; xi[i] = ai + bi; xr[i+2] = ar - br; xi[i+2] = ai - bi; }
        { float ar = xr[i+1], ai = xi[i+1], br = xr[i+3], bi = xi[i+3];
          float wr = -sgn * bi, wi = sgn * br;
          xr[i+1] = ar + wr; xi[i+1] = ai + wi; xr[i+3] = ar - wr; xi[i+3] = ai - wi; }
    }
    const float c = 0.70710678118654752f;
    { float ar = xr[0], ai = xi[0], br = xr[4], bi = xi[4];
      xr[0] = ar + br; xi[0] = ai + bi; xr[4] = ar - br; xi[4] = ai - bi; }
    { float ar = xr[1], ai = xi[1], br = xr[5], bi = xi[5];
      float wr = c * (br - sgn * bi), wi = c * (bi + sgn * br);
      xr[1] = ar + wr; xi[1] = ai + wi; xr[5] = ar - wr; xi[5] = ai - wi; }
    { float ar = xr[2], ai = xi[2], br = xr[6], bi = xi[6];
      float wr = -sgn * bi, wi = sgn * br;
      xr[2] = ar + wr; xi[2] = ai + wi; xr[6] = ar - wr; xi[6] = ai - wi; }
    { float ar = xr[3], ai = xi[3], br = xr[7], bi = xi[7];
      float wr = c * (-br - sgn * bi), wi = c * (-bi + sgn * br);
      xr[3] = ar + wr; xi[3] = ai + wi; xr[7] = ar - wr; xi[7] = ai - wi; }
}

__device__ __forceinline__ void fft_filter_store(int oc, const f32x2_t* acc,
                                                 const float* __restrict__ filt,
                                                 int b, int ph, int pw) {
    float a[64];
    #pragma unroll
    for (int j = 0; j < 32; j++) unpack2(acc[j], a[2*j], a[2*j+1]);

    float re[8][5], im[8][5];
    #pragma unroll
    for (int r = 0; r < 8; r++) {
        float xr[8], xi[8];
        #pragma unroll
        for (int c = 0; c < 8; c++) { xr[c] = a[r*8 + c]; xi[c] = 0.f; }
        fft8(xr, xi, -1.f);
        #pragma unroll
        for (int k = 0; k < 5; k++) { re[r][k] = xr[k]; im[r][k] = xi[k]; }
    }
    const float* fch = filt + oc * 40;
    #pragma unroll
    for (int k = 0; k < 5; k++) {
        float xr[8], xi[8];
        #pragma unroll
        for (int r = 0; r < 8; r++) { xr[r] = re[r][k]; xi[r] = im[r][k]; }
        fft8(xr, xi, -1.f);
        #pragma unroll
        for (int r = 0; r < 8; r++) {
            float f = __ldg(fch + r*5 + k) * (1.f / 64.f);
            xr[r] *= f; xi[r] *= f;
        }
        fft8(xr, xi, 1.f);
        #pragma unroll
        for (int r = 0; r < 8; r++) { re[r][k] = xr[r]; im[r][k] = xi[r]; }
    }
    float* ob = g_t + (((size_t)(b * C2 + oc) * HW + ph*8) * HW + pw*8);
    #pragma unroll
    for (int r = 0; r < 8; r++) {
        float xr[8], xi[8];
        #pragma unroll
        for (int k = 0; k < 5; k++) { xr[k] = re[r][k]; xi[k] = im[r][k]; }
        xr[5] = re[r][3]; xi[5] = -im[r][3];
        xr[6] = re[r][2]; xi[6] = -im[r][2];
        xr[7] = re[r][1]; xi[7] = -im[r][1];
        fft8(xr, xi, 1.f);
        float4 v0 = make_float4(xr[0], xr[1], xr[2], xr[3]);
        float4 v1 = make_float4(xr[4], xr[5], xr[6], xr[7]);
        *(float4*)(ob + (size_t)r * HW)     = v0;
        *(float4*)(ob + (size_t)r * HW + 4) = v1;
    }
}

// ================= Kernel A: project_in (64->340) + patch FFT filter =================
// (byte-identical to the measured R5/R12 version)
#define KA_THREADS 176
#define SMEM_A (64*64*4 + C2*DIMIN*4)   // patch (16KB) + transposed W_in (87KB)

__global__ void __launch_bounds__(KA_THREADS, 2)
kA(const float* __restrict__ x, const float* __restrict__ Win,
   const float* __restrict__ filt) {
    extern __shared__ float sm[];
    float* sX = sm;             // [ic][64 pix]
    float* sW = sm + 64 * 64;   // transposed: [ic][oc]

    const int t  = threadIdx.x;
    const int pw = blockIdx.x, ph = blockIdx.y, b = blockIdx.z;

    for (int i = t; i < 1024; i += KA_THREADS) {
        int ic = i >> 4, rr = (i >> 1) & 7, half = i & 1;
        float4 v = *(const float4*)(x + (((size_t)(b * DIMIN + ic) * HW + ph*8 + rr) * HW + pw*8 + half*4));
        *(float4*)(sX + ic*64 + rr*8 + half*4) = v;
    }
    for (int i = t; i < C2 * DIMIN; i += KA_THREADS) {
        int oc = i >> 6, ic = i & 63;
        sW[ic * C2 + oc] = Win[i];
    }
    __syncthreads();

    const int oc0 = t;
    const int oc1 = t + KA_THREADS;
    const bool has1 = (oc1 < C2);
    const int oc1c = has1 ? oc1 : 0;

    f32x2_t a0[32], a1[32];
    #pragma unroll
    for (int j = 0; j < 32; j++) { a0[j] = 0ull; a1[j] = 0ull; }

    const ulonglong2* sX4 = (const ulonglong2*)sX;
    #pragma unroll 2
    for (int ic = 0; ic < 64; ic++) {
        f32x2_t w0 = dup2(sW[ic * C2 + oc0]);
        f32x2_t w1 = dup2(sW[ic * C2 + oc1c]);
        #pragma unroll
        for (int j = 0; j < 16; j++) {
            ulonglong2 xv = sX4[ic * 16 + j];
            a0[2*j]   = ffma2(w0, xv.x, a0[2*j]);
            a0[2*j+1] = ffma2(w0, xv.y, a0[2*j+1]);
            a1[2*j]   = ffma2(w1, xv.x, a1[2*j]);
            a1[2*j+1] = ffma2(w1, xv.y, a1[2*j+1]);
        }
    }
    __syncthreads();

    f32x2_t* sSpill = (f32x2_t*)sm;   // [32][KA_THREADS]
    #pragma unroll
    for (int j = 0; j < 32; j++) sSpill[j * KA_THREADS + t] = a1[j];

    fft_filter_store(oc0, a0, filt, b, ph, pw);

    if (has1) {
        f32x2_t a1b[32];
        #pragma unroll
        for (int j = 0; j < 32; j++) a1b[j] = sSpill[j * KA_THREADS + t];
        fft_filter_store(oc1, a1b, filt, b, ph, pw);
    }
}

// ============ Kernel B: depthwise 3x3 + GELU gate + project_out (170->64) ============
// cp.async DOUBLE-BUFFERED halo pipeline: chunk = 8 channel-pairs (16 ch), 22 chunks.
// While chunk cc is computed (phase B: dw+GELU -> sG; phase C: GEMM update), chunk
// cc+1's halo streams into the spare sT buffer via 4-byte cp.async with runtime
// src-size (0 => zero-fill for out-of-image). 2 barriers per chunk.
#define NCHK    8                                  // channel-pairs per chunk
#define NCHUNK  22                                 // ceil(170/8); last chunk has 2
#define STBUF_F (2 * NCHK * 324)
#define SWO_F   (HID * 64)
#define SDW_F   (C2 * 9)
#define SG_F    (NCHK * 256)
#define SMEM_B  ((SWO_F + SDW_F + 2 * STBUF_F + SG_F) * 4)   // 105,424 bytes

__global__ void __launch_bounds__(256, 2)
kB(const float* __restrict__ Wdw, const float* __restrict__ Wout,
   float* __restrict__ out) {
    extern __shared__ float sm[];
    float* sWo = sm;                               // transposed: [hc][64 o]
    float* sDw = sm + SWO_F;                       // [340*9]
    float* sT0 = sm + SWO_F + SDW_F;               // buffer 0: [16][324]
    float* sT1 = sT0 + STBUF_F;                    // buffer 1
    float* sG  = sT1 + STBUF_F;                    // [8][256]

    const int t  = threadIdx.x;
    const int tx = t & 15, ty = t >> 4;
    const int bx = blockIdx.x * 16, by = blockIdx.y * 16, b = blockIdx.z;

    const int outg = t >> 5;
    const int p0   = (t & 31) * 8;

    // ---- halo slot mapping (once): slot1 = t, slot2 = 256 + t (t < 68) ----
    const int ly1 = t / 18, lx1 = t % 18;
    const int ly2 = (t + 256) / 18, lx2 = (t + 256) % 18;
    const bool ok1 = (by - 1 + ly1 >= 0) && (by - 1 + ly1 < HW) &&
                     (bx - 1 + lx1 >= 0) && (bx - 1 + lx1 < HW);
    const bool has2 = (t < 68);
    const bool ok2 = has2 && (by - 1 + ly2 >= 0) && (by - 1 + ly2 < HW) &&
                     (bx - 1 + lx2 >= 0) && (bx - 1 + lx2 < HW);
    const int off1 = ok1 ? ((by - 1 + ly1) * HW + (bx - 1 + lx1)) : 0;
    const int off2 = ok2 ? ((by - 1 + ly2) * HW + (bx - 1 + lx2)) : 0;
    const int sz1 = ok1 ? 4 : 0;
    const int sz2 = ok2 ? 4 : 0;
    const float* gbase = g_t + (size_t)b * C2 * (HW * HW);

    const unsigned sT0a = (unsigned)__cvta_generic_to_shared(sT0);
    const unsigned sT1a = (unsigned)__cvta_generic_to_shared(sT1);

    // ---- prologue: kick off chunk 0's halo, then stage weights ----
    {
        const float* a0 = gbase;
        const float* b0 = gbase + (size_t)HID * (HW * HW);
        #pragma unroll 4
        for (int ch = 0; ch < NCHK; ch++) {
            const float* pa = a0 + (size_t)ch * (HW * HW);
            const float* pb = b0 + (size_t)ch * (HW * HW);
            unsigned da = sT0a + (unsigned)(ch * 324 + t) * 4;
            unsigned db = sT0a + (unsigned)((NCHK + ch) * 324 + t) * 4;
            cpasync4(da, pa + off1, sz1);
            cpasync4(db, pb + off1, sz1);
            if (has2) {
                cpasync4(da + 1024, pa + off2, sz2);
                cpasync4(db + 1024, pb + off2, sz2);
            }
        }
        cpasync_commit();
    }

    for (int i = t; i < DIMIN * HID; i += 256) {
        int o = i / HID, hc = i % HID;
        sWo[hc * 64 + o] = Wout[i];
    }
    for (int i = t; i < C2 * 9; i += 256) sDw[i] = Wdw[i];

    f32x2_t acc[8][4];
    #pragma unroll
    for (int o = 0; o < 8; o++)
        #pragma unroll
        for (int pp = 0; pp < 4; pp++) acc[o][pp] = 0ull;

    for (int cc = 0; cc < NCHUNK; cc++) {
        float* sT = (cc & 1) ? sT1 : sT0;
        const int nch = (cc == NCHUNK - 1) ? (HID - NCHK * (NCHUNK - 1)) : NCHK;

        // ---- prefetch chunk cc+1 into the spare buffer ----
        if (cc + 1 < NCHUNK) {
            unsigned sd = ((cc + 1) & 1) ? sT1a : sT0a;
            const int base = (cc + 1) * NCHK;
            const int nnext = (cc + 1 == NCHUNK - 1) ? (HID - NCHK * (NCHUNK - 1)) : NCHK;
            const float* a0 = gbase + (size_t)base * (HW * HW);
            const float* b0 = gbase + (size_t)(HID + base) * (HW * HW);
            #pragma unroll 4
            for (int ch = 0; ch < nnext; ch++) {
                const float* pa = a0 + (size_t)ch * (HW * HW);
                const float* pb = b0 + (size_t)ch * (HW * HW);
                unsigned da = sd + (unsigned)(ch * 324 + t) * 4;
                unsigned db = sd + (unsigned)((NCHK + ch) * 324 + t) * 4;
                cpasync4(da, pa + off1, sz1);
                cpasync4(db, pb + off1, sz1);
                if (has2) {
                    cpasync4(da + 1024, pa + off2, sz2);
                    cpasync4(db + 1024, pb + off2, sz2);
                }
            }
        }
        cpasync_commit();          // empty group on last iteration keeps count simple
        cpasync_wait1();           // chunk cc's data has landed
        __syncthreads();           // visibility + sG write-after-read ordering

        // -------- phase B: dw conv + exact GELU gate -> sG --------
        for (int c = 0; c < nch; c++) {
            int hc = cc * NCHK + c;
            const float* w1 = sDw + hc * 9;
            const float* w2 = sDw + (hc + HID) * 9;
            const float* t1 = sT + c * 324 + ty * 18 + tx;
            const float* t2 = t1 + NCHK * 324;
            float d1 = 0.f, d2 = 0.f;
            #pragma unroll
            for (int ky = 0; ky < 3; ky++)
                #pragma unroll
                for (int kx = 0; kx < 3; kx++) {
                    d1 = fmaf(w1[ky*3 + kx], t1[ky*18 + kx], d1);
                    d2 = fmaf(w2[ky*3 + kx], t2[ky*18 + kx], d2);
                }
            float g = 0.5f * d1 * (1.f + erff(d1 * 0.70710678118654752f)) * d2;
            sG[c * 256 + t] = g;
        }
        __syncthreads();           // sG ready; phase B done reading sT

        // -------- phase C: projection GEMM update (k = nch) --------
        for (int c = 0; c < nch; c++) {
            int hc = cc * NCHK + c;
            const ulonglong2* gp = (const ulonglong2*)(sG + c * 256 + p0);
            ulonglong2 gv0 = gp[0], gv1 = gp[1];
            const float4* wp = (const float4*)(sWo + hc * 64 + outg * 8);
            float4 w0 = wp[0], w1 = wp[1];
            f32x2_t wd[8];
            wd[0] = dup2(w0.x); wd[1] = dup2(w0.y); wd[2] = dup2(w0.z); wd[3] = dup2(w0.w);
            wd[4] = dup2(w1.x); wd[5] = dup2(w1.y); wd[6] = dup2(w1.z); wd[7] = dup2(w1.w);
            #pragma unroll
            for (int o = 0; o < 8; o++) {
                acc[o][0] = ffma2(wd[o], gv0.x, acc[o][0]);
                acc[o][1] = ffma2(wd[o], gv0.y, acc[o][1]);
                acc[o][2] = ffma2(wd[o], gv1.x, acc[o][2]);
                acc[o][3] = ffma2(wd[o], gv1.y, acc[o][3]);
            }
        }
        // no trailing sync: next iteration's top barrier orders sG reuse; the
        // prefetch it issues targets the buffer whose last readers (this phase B)
        // all passed the post-B barrier above.
    }

    // -------- store: thread owns outputs (outg*8..+7) x pixels (p0..p0+7) --------
    const int py  = p0 >> 4;
    const int px0 = p0 & 15;
    #pragma unroll
    for (int o = 0; o < 8; o++) {
        int oc = outg * 8 + o;
        float v[8];
        #pragma unroll
        for (int pp = 0; pp < 4; pp++) unpack2(acc[o][pp], v[2*pp], v[2*pp+1]);
        float* ob = out + (((size_t)(b * DIMIN + oc)) * HW + (by + py)) * HW + (bx + px0);
        *(float4*)(ob)     = make_float4(v[0], v[1], v[2], v[3]);
        *(float4*)(ob + 4) = make_float4(v[4], v[5], v[6], v[7]);
    }
}

// ======================== launch ========================
extern "C" void kernel_launch(void* const* d_in, const int* in_sizes, int n_in,
                              void* d_out, int out_size) {
    (void)in_sizes; (void)n_in; (void)out_size;
    const float* x    = (const float*)d_in[0];
    const float* Win  = (const float*)d_in[1];
    const float* Wdw  = (const float*)d_in[2];
    const float* filt = (const float*)d_in[3];
    const float* Wout = (const float*)d_in[4];
    float* out = (float*)d_out;

    cudaFuncSetAttribute(kA, cudaFuncAttributeMaxDynamicSharedMemorySize, SMEM_A);
    cudaFuncSetAttribute(kB, cudaFuncAttributeMaxDynamicSharedMemorySize, SMEM_B);

    kA<<<dim3(32, 32, BATCH), KA_THREADS, SMEM_A>>>(x, Win, filt);
    kB<<<dim3(16, 16, BATCH), 256, SMEM_B>>>(Wdw, Wout, out);
}

// round 16
// speedup vs baseline: 1.5808x; 1.0067x over previous
#include <cuda_runtime.h>
#include <cstdint>

#define DIMIN 64
#define HID   170
#define C2    340
#define BATCH 4
#define HW    256

typedef unsigned long long f32x2_t;   // packed pair of fp32

// Intermediate buffer t = FFT-filtered projection, [4,340,256,256] fp32 (356MB scratch)
__device__ float g_t[(size_t)BATCH * C2 * HW * HW];

// ---------- packed f32x2 helpers ----------
__device__ __forceinline__ f32x2_t ffma2(f32x2_t a, f32x2_t b, f32x2_t c) {
    f32x2_t d;
    asm("fma.rn.f32x2 %0, %1, %2, %3;" : "=l"(d) : "l"(a), "l"(b), "l"(c));
    return d;
}
__device__ __forceinline__ f32x2_t dup2(float v) {
    f32x2_t d;
    asm("mov.b64 %0, {%1, %1};" : "=l"(d) : "f"(v));
    return d;
}
__device__ __forceinline__ void unpack2(f32x2_t v, float& lo, float& hi) {
    asm("mov.b64 {%0, %1}, %2;" : "=f"(lo), "=f"(hi) : "l"(v));
}

// ---------- cp.async helpers ----------
__device__ __forceinline__ void cpasync8(unsigned dst, const float* src, int szbytes) {
    asm volatile("cp.async.ca.shared.global [%0], [%1], 8, %2;"
                 :: "r"(dst), "l"(src), "r"(szbytes) : "memory");
}
__device__ __forceinline__ void cpasync_commit() {
    asm volatile("cp.async.commit_group;" ::: "memory");
}
__device__ __forceinline__ void cpasync_wait1() {
    asm volatile("cp.async.wait_group 1;" ::: "memory");
}

// ---------- unrolled 8-point complex FFT (sgn=-1 fwd, +1 inv, unnormalized) ----------
__device__ __forceinline__ void fft8(float* xr, float* xi, float sgn) {
    float tr, ti;
    tr = xr[1]; xr[1] = xr[4]; xr[4] = tr;  ti = xi[1]; xi[1] = xi[4]; xi[4] = ti;
    tr = xr[3]; xr[3] = xr[6]; xr[6] = tr;  ti = xi[3]; xi[3] = xi[6]; xi[6] = ti;
    #pragma unroll
    for (int i = 0; i < 8; i += 2) {
        float ar = xr[i], ai = xi[i], br = xr[i+1], bi = xi[i+1];
        xr[i] = ar + br; xi[i] = ai + bi; xr[i+1] = ar - br; xi[i+1] = ai - bi;
    }
    #pragma unroll
    for (int i = 0; i < 8; i += 4) {
        { float ar = xr[i], ai = xi[i], br = xr[i+2], bi = xi[i+2];
          xr[i] = ar + br; xi[i] = ai + bi; xr[i+2] = ar - br; xi[i+2] = ai - bi; }
        { float ar = xr[i+1], ai = xi[i+1], br = xr[i+3], bi = xi[i+3];
          float wr = -sgn * bi, wi = sgn * br;
          xr[i+1] = ar + wr; xi[i+1] = ai + wi; xr[i+3] = ar - wr; xi[i+3] = ai - wi; }
    }
    const float c = 0.70710678118654752f;
    { float ar = xr[0], ai = xi[0], br = xr[4], bi = xi[4];
      xr[0] = ar + br; xi[0] = ai + bi; xr[4] = ar - br; xi[4] = ai - bi; }
    { float ar = xr[1], ai = xi[1], br = xr[5], bi = xi[5];
      float wr = c * (br - sgn * bi), wi = c * (bi + sgn * br);
      xr[1] = ar + wr; xi[1] = ai + wi; xr[5] = ar - wr; xi[5] = ai - wi; }
    { float ar = xr[2], ai = xi[2], br = xr[6], bi = xi[6];
      float wr = -sgn * bi, wi = sgn * br;
      xr[2] = ar + wr; xi[2] = ai + wi; xr[6] = ar - wr; xi[6] = ai - wi; }
    { float ar = xr[3], ai = xi[3], br = xr[7], bi = xi[7];
      float wr = c * (-br - sgn * bi), wi = c * (-bi + sgn * br);
      xr[3] = ar + wr; xi[3] = ai + wi; xr[7] = ar - wr; xi[7] = ai - wi; }
}

__device__ __forceinline__ void fft_filter_store(int oc, const f32x2_t* acc,
                                                 const float* __restrict__ filt,
                                                 int b, int ph, int pw) {
    float a[64];
    #pragma unroll
    for (int j = 0; j < 32; j++) unpack2(acc[j], a[2*j], a[2*j+1]);

    float re[8][5], im[8][5];
    #pragma unroll
    for (int r = 0; r < 8; r++) {
        float xr[8], xi[8];
        #pragma unroll
        for (int c = 0; c < 8; c++) { xr[c] = a[r*8 + c]; xi[c] = 0.f; }
        fft8(xr, xi, -1.f);
        #pragma unroll
        for (int k = 0; k < 5; k++) { re[r][k] = xr[k]; im[r][k] = xi[k]; }
    }
    const float* fch = filt + oc * 40;
    #pragma unroll
    for (int k = 0; k < 5; k++) {
        float xr[8], xi[8];
        #pragma unroll
        for (int r = 0; r < 8; r++) { xr[r] = re[r][k]; xi[r] = im[r][k]; }
        fft8(xr, xi, -1.f);
        #pragma unroll
        for (int r = 0; r < 8; r++) {
            float f = __ldg(fch + r*5 + k) * (1.f / 64.f);
            xr[r] *= f; xi[r] *= f;
        }
        fft8(xr, xi, 1.f);
        #pragma unroll
        for (int r = 0; r < 8; r++) { re[r][k] = xr[r]; im[r][k] = xi[r]; }
    }
    float* ob = g_t + (((size_t)(b * C2 + oc) * HW + ph*8) * HW + pw*8);
    #pragma unroll
    for (int r = 0; r < 8; r++) {
        float xr[8], xi[8];
        #pragma unroll
        for (int k = 0; k < 5; k++) { xr[k] = re[r][k]; xi[k] = im[r][k]; }
        xr[5] = re[r][3]; xi[5] = -im[r][3];
        xr[6] = re[r][2]; xi[6] = -im[r][2];
        xr[7] = re[r][1]; xi[7] = -im[r][1];
        fft8(xr, xi, 1.f);
        float4 v0 = make_float4(xr[0], xr[1], xr[2], xr[3]);
        float4 v1 = make_float4(xr[4], xr[5], xr[6], xr[7]);
        *(float4*)(ob + (size_t)r * HW)     = v0;
        *(float4*)(ob + (size_t)r * HW + 4) = v1;
    }
}

// ================= Kernel A: project_in (64->340) + patch FFT filter =================
// (byte-identical to the measured R5/R13 version)
#define KA_THREADS 176
#define SMEM_A (64*64*4 + C2*DIMIN*4)   // patch (16KB) + transposed W_in (87KB)

__global__ void __launch_bounds__(KA_THREADS, 2)
kA(const float* __restrict__ x, const float* __restrict__ Win,
   const float* __restrict__ filt) {
    extern __shared__ float sm[];
    float* sX = sm;             // [ic][64 pix]
    float* sW = sm + 64 * 64;   // transposed: [ic][oc]

    const int t  = threadIdx.x;
    const int pw = blockIdx.x, ph = blockIdx.y, b = blockIdx.z;

    for (int i = t; i < 1024; i += KA_THREADS) {
        int ic = i >> 4, rr = (i >> 1) & 7, half = i & 1;
        float4 v = *(const float4*)(x + (((size_t)(b * DIMIN + ic) * HW + ph*8 + rr) * HW + pw*8 + half*4));
        *(float4*)(sX + ic*64 + rr*8 + half*4) = v;
    }
    for (int i = t; i < C2 * DIMIN; i += KA_THREADS) {
        int oc = i >> 6, ic = i & 63;
        sW[ic * C2 + oc] = Win[i];
    }
    __syncthreads();

    const int oc0 = t;
    const int oc1 = t + KA_THREADS;
    const bool has1 = (oc1 < C2);
    const int oc1c = has1 ? oc1 : 0;

    f32x2_t a0[32], a1[32];
    #pragma unroll
    for (int j = 0; j < 32; j++) { a0[j] = 0ull; a1[j] = 0ull; }

    const ulonglong2* sX4 = (const ulonglong2*)sX;
    #pragma unroll 2
    for (int ic = 0; ic < 64; ic++) {
        f32x2_t w0 = dup2(sW[ic * C2 + oc0]);
        f32x2_t w1 = dup2(sW[ic * C2 + oc1c]);
        #pragma unroll
        for (int j = 0; j < 16; j++) {
            ulonglong2 xv = sX4[ic * 16 + j];
            a0[2*j]   = ffma2(w0, xv.x, a0[2*j]);
            a0[2*j+1] = ffma2(w0, xv.y, a0[2*j+1]);
            a1[2*j]   = ffma2(w1, xv.x, a1[2*j]);
            a1[2*j+1] = ffma2(w1, xv.y, a1[2*j+1]);
        }
    }
    __syncthreads();

    f32x2_t* sSpill = (f32x2_t*)sm;   // [32][KA_THREADS]
    #pragma unroll
    for (int j = 0; j < 32; j++) sSpill[j * KA_THREADS + t] = a1[j];

    fft_filter_store(oc0, a0, filt, b, ph, pw);

    if (has1) {
        f32x2_t a1b[32];
        #pragma unroll
        for (int j = 0; j < 32; j++) a1b[j] = sSpill[j * KA_THREADS + t];
        fft_filter_store(oc1, a1b, filt, b, ph, pw);
    }
}

// ============ Kernel B: depthwise 3x3 + GELU gate + project_out (170->64) ============
// R13 double-buffered cp.async pipeline with 8-byte halo segments.
// FIX vs R14: gate-b channels always land at slot NCHK + ch (matching phase B's
// fixed t2 offset), independent of the chunk's channel count.
#define NCHK    8                                  // channel-pairs per chunk
#define NCHUNK  22                                 // ceil(170/8); last chunk has 2
#define ROWW    20                                 // sT row width (cols bx-2..bx+17)
#define CHF     (18 * ROWW)                        // floats per channel tile = 360
#define STBUF_F (2 * NCHK * CHF)                   // 5760 floats per buffer
#define SWO_F   (HID * 64)
#define SDW_F   (C2 * 9)
#define SG_F    (NCHK * 256)
#define SMEM_B  ((SWO_F + SDW_F + 2 * STBUF_F + SG_F) * 4)   // 110,032 bytes

__global__ void __launch_bounds__(256, 2)
kB(const float* __restrict__ Wdw, const float* __restrict__ Wout,
   float* __restrict__ out) {
    extern __shared__ float sm[];
    float* sWo = sm;                               // transposed: [hc][64 o]
    float* sDw = sm + SWO_F;                       // [340*9]
    float* sT0 = sm + SWO_F + SDW_F;               // buffer 0: [16][18][20]
    float* sT1 = sT0 + STBUF_F;                    // buffer 1
    float* sG  = sT1 + STBUF_F;                    // [8][256]

    const int t  = threadIdx.x;
    const int tx = t & 15, ty = t >> 4;
    const int bx = blockIdx.x * 16, by = blockIdx.y * 16, b = blockIdx.z;

    const int outg = t >> 5;
    const int p0   = (t & 31) * 8;

    const float* gbase = g_t + (size_t)b * C2 * (HW * HW);
    const unsigned sT0a = (unsigned)__cvta_generic_to_shared(sT0);
    const unsigned sT1a = (unsigned)__cvta_generic_to_shared(sT1);

    // Halo loader: load npair channel-pairs (both halves) of chunk starting at
    // channel `base` into buffer `sd`. Row = 10 x 8-byte segments covering
    // columns bx-2..bx+17. seg 0 OOB iff bx==0; seg 9 OOB iff bx>=HW-16; rows
    // via gy predicate (src-size 0 => zero-fill).
    // Slot layout FIX: gate-a channel ch -> slot ch; gate-b channel ch -> slot
    // NCHK + ch (fixed, so phase B's t2 = t1 + NCHK*CHF holds for ALL chunks).
    #define HALO_LOAD(sd, base, npair)                                          \
    {                                                                           \
        const int nseg = (npair) * 2 * 180;                                     \
        for (int i = t; i < nseg; i += 256) {                                   \
            int c2  = i / 180;                                                  \
            int pos = i % 180;                                                  \
            int row = pos / 10;                                                 \
            int seg = pos % 10;                                                 \
            int gy  = by - 1 + row;                                             \
            bool ok = (gy >= 0) && (gy < HW) &&                                 \
                      (seg > 0 || bx > 0) && (seg < 9 || bx < HW - 16);         \
            bool isB = (c2 >= (npair));                                         \
            int ch   = isB ? (c2 - (npair)) : c2;                               \
            int chg  = (base) + ch + (isB ? HID : 0);                           \
            int slot = ch + (isB ? NCHK : 0);                                   \
            const float* src = gbase + (size_t)chg * (HW * HW)                  \
                               + (ok ? (gy * HW + bx - 2 + seg * 2) : 0);       \
            unsigned dst = (sd) + (unsigned)(slot * CHF + row * ROWW + seg * 2) * 4; \
            cpasync8(dst, src, ok ? 8 : 0);                                     \
        }                                                                       \
    }

    // ---- prologue: kick off chunk 0's halo, then stage weights ----
    HALO_LOAD(sT0a, 0, NCHK);
    cpasync_commit();

    for (int i = t; i < DIMIN * HID; i += 256) {
        int o = i / HID, hc = i % HID;
        sWo[hc * 64 + o] = Wout[i];
    }
    for (int i = t; i < C2 * 9; i += 256) sDw[i] = Wdw[i];

    f32x2_t acc[8][4];
    #pragma unroll
    for (int o = 0; o < 8; o++)
        #pragma unroll
        for (int pp = 0; pp < 4; pp++) acc[o][pp] = 0ull;

    for (int cc = 0; cc < NCHUNK; cc++) {
        float* sT = (cc & 1) ? sT1 : sT0;
        const int nch = (cc == NCHUNK - 1) ? (HID - NCHK * (NCHUNK - 1)) : NCHK;

        // ---- prefetch chunk cc+1 into the spare buffer ----
        if (cc + 1 < NCHUNK) {
            unsigned sd = ((cc + 1) & 1) ? sT1a : sT0a;
            const int base = (cc + 1) * NCHK;
            const int nnext = (cc + 1 == NCHUNK - 1) ? (HID - NCHK * (NCHUNK - 1)) : NCHK;
            HALO_LOAD(sd, base, nnext);
        }
        cpasync_commit();          // empty group on last iteration keeps count simple
        cpasync_wait1();           // chunk cc's data has landed
        __syncthreads();           // visibility + sG write-after-read ordering

        // -------- phase B: dw conv + exact GELU gate -> sG --------
        for (int c = 0; c < nch; c++) {
            int hc = cc * NCHK + c;
            const float* w1 = sDw + hc * 9;
            const float* w2 = sDw + (hc + HID) * 9;
            const float* t1 = sT + c * CHF + ty * ROWW + tx + 1;   // +1: col bx-1 at idx 1
            const float* t2 = t1 + NCHK * CHF;
            float d1 = 0.f, d2 = 0.f;
            #pragma unroll
            for (int ky = 0; ky < 3; ky++)
                #pragma unroll
                for (int kx = 0; kx < 3; kx++) {
                    d1 = fmaf(w1[ky*3 + kx], t1[ky*ROWW + kx], d1);
                    d2 = fmaf(w2[ky*3 + kx], t2[ky*ROWW + kx], d2);
                }
            float g = 0.5f * d1 * (1.f + erff(d1 * 0.70710678118654752f)) * d2;
            sG[c * 256 + t] = g;
        }
        __syncthreads();           // sG ready; phase B done reading sT

        // -------- phase C: projection GEMM update (k = nch) --------
        for (int c = 0; c < nch; c++) {
            int hc = cc * NCHK + c;
            const ulonglong2* gp = (const ulonglong2*)(sG + c * 256 + p0);
            ulonglong2 gv0 = gp[0], gv1 = gp[1];
            const float4* wp = (const float4*)(sWo + hc * 64 + outg * 8);
            float4 w0 = wp[0], w1 = wp[1];
            f32x2_t wd[8];
            wd[0] = dup2(w0.x); wd[1] = dup2(w0.y); wd[2] = dup2(w0.z); wd[3] = dup2(w0.w);
            wd[4] = dup2(w1.x); wd[5] = dup2(w1.y); wd[6] = dup2(w1.z); wd[7] = dup2(w1.w);
            #pragma unroll
            for (int o = 0; o < 8; o++) {
                acc[o][0] = ffma2(wd[o], gv0.x, acc[o][0]);
                acc[o][1] = ffma2(wd[o], gv0.y, acc[o][1]);
                acc[o][2] = ffma2(wd[o], gv1.x, acc[o][2]);
                acc[o][3] = ffma2(wd[o], gv1.y, acc[o][3]);
            }
        }
        // no trailing sync: next iteration's top barrier orders sG reuse; the
        // prefetch it issues targets the buffer whose last readers (this phase B)
        // all passed the post-B barrier above.
    }

    // -------- store: thread owns outputs (outg*8..+7) x pixels (p0..p0+7) --------
    const int py  = p0 >> 4;
    const int px0 = p0 & 15;
    #pragma unroll
    for (int o = 0; o < 8; o++) {
        int oc = outg * 8 + o;
        float v[8];
        #pragma unroll
        for (int pp = 0; pp < 4; pp++) unpack2(acc[o][pp], v[2*pp], v[2*pp+1]);
        float* ob = out + (((size_t)(b * DIMIN + oc)) * HW + (by + py)) * HW + (bx + px0);
        *(float4*)(ob)     = make_float4(v[0], v[1], v[2], v[3]);
        *(float4*)(ob + 4) = make_float4(v[4], v[5], v[6], v[7]);
    }
}

// ======================== launch ========================
extern "C" void kernel_launch(void* const* d_in, const int* in_sizes, int n_in,
                              void* d_out, int out_size) {
    (void)in_sizes; (void)n_in; (void)out_size;
    const float* x    = (const float*)d_in[0];
    const float* Win  = (const float*)d_in[1];
    const float* Wdw  = (const float*)d_in[2];
    const float* filt = (const float*)d_in[3];
    const float* Wout = (const float*)d_in[4];
    float* out = (float*)d_out;

    cudaFuncSetAttribute(kA, cudaFuncAttributeMaxDynamicSharedMemorySize, SMEM_A);
    cudaFuncSetAttribute(kB, cudaFuncAttributeMaxDynamicSharedMemorySize, SMEM_B);

    kA<<<dim3(32, 32, BATCH), KA_THREADS, SMEM_A>>>(x, Win, filt);
    kB<<<dim3(16, 16, BATCH), 256, SMEM_B>>>(Wdw, Wout, out);
}